// round 1
// baseline (speedup 1.0000x reference)
#include <cuda_runtime.h>
#include <math.h>

// NTXent fused kernel — Round 1 baseline (fp32 SIMT tiled GEMM, fused epilogue).
//
// reference:
//   S[i,j] = dot(a_i, p_j) / max(||a_i||*||p_j||, eps)
//   loss_i = logsumexp(S[i,:]/T) - S[i,i]/T        (T = 0.25)
//   out = (mean(loss), mean(diag(S)), mean((rowsum(S)-diag)/(B-1)))
//
// |S| <= 1 -> logits in [-4,4] -> plain log(sum(exp)) is numerically safe
// (no max-subtraction pass needed).

#define B_SIZE 8192
#define D_SIZE 626
#define INV_TEMP 4.0f

#define BM 128
#define BN 128
#define BK 16
#define PAD 4   // keeps 16B alignment for float4 smem reads

// persistent scratch (allocation-free rule: __device__ globals)
__device__ float g_rna[B_SIZE];     // 1/||anchor_i||
__device__ float g_rnp[B_SIZE];     // 1/||pos_j||
__device__ float g_sumexp[B_SIZE];  // sum_j exp(S_ij/T)
__device__ float g_sumS[B_SIZE];    // sum_j S_ij
__device__ float g_diag[B_SIZE];    // S_ii

// ---------------------------------------------------------------------------
// init: inverse norms + zero accumulators + zero output
// grid: (B/8, 2), block 256 (8 warps; 1 warp per row)
// ---------------------------------------------------------------------------
__global__ void __launch_bounds__(256) ntxent_init(const float* __restrict__ A,
                                                   const float* __restrict__ P,
                                                   float* __restrict__ out) {
    const int warp = threadIdx.x >> 5;
    const int lane = threadIdx.x & 31;
    const int row  = blockIdx.x * 8 + warp;
    const float* X = blockIdx.y ? P : A;

    float ss = 0.f;
    const float* xr = X + (size_t)row * D_SIZE;
    for (int c = lane; c < D_SIZE; c += 32) {
        float v = xr[c];
        ss = fmaf(v, v, ss);
    }
    #pragma unroll
    for (int off = 16; off; off >>= 1)
        ss += __shfl_down_sync(0xffffffffu, ss, off);

    if (lane == 0) {
        float rn = 1.0f / sqrtf(ss);   // norms ~25, eps clamp irrelevant
        if (blockIdx.y == 0) {
            g_rna[row] = rn;
            g_sumexp[row] = 0.f;
            g_sumS[row] = 0.f;
        } else {
            g_rnp[row] = rn;
        }
    }
    if (blockIdx.x == 0 && blockIdx.y == 0 && threadIdx.x < 3)
        out[threadIdx.x] = 0.f;
}

// ---------------------------------------------------------------------------
// main: 128x128 output tile per CTA, full K loop, fused NTXent epilogue
// 256 threads, 8x8 per thread (4+4 / 4+4 fragment split: conflict-free smem)
// ---------------------------------------------------------------------------
__global__ void __launch_bounds__(256) ntxent_main(const float* __restrict__ A,
                                                   const float* __restrict__ P) {
    __shared__ float As[BK][BM + PAD];
    __shared__ float Bs[BK][BN + PAD];

    const int tid = threadIdx.x;
    const int m0 = blockIdx.y * BM;
    const int n0 = blockIdx.x * BN;
    const int tm = tid >> 4;   // 0..15
    const int tn = tid & 15;   // 0..15

    // loader mapping: lk = k within tile, lm = base row; 8 rows per thread
    const int lk = tid & 15;
    const int lm = tid >> 4;

    float acc[8][8];
    #pragma unroll
    for (int i = 0; i < 8; i++)
        #pragma unroll
        for (int j = 0; j < 8; j++) acc[i][j] = 0.f;

    for (int k0 = 0; k0 < D_SIZE; k0 += BK) {
        const int gk = k0 + lk;
        const bool kok = (gk < D_SIZE);
        #pragma unroll
        for (int l = 0; l < 8; l++) {
            const int m = lm + l * 16;
            As[lk][m] = kok ? A[(size_t)(m0 + m) * D_SIZE + gk] : 0.f;
            Bs[lk][m] = kok ? P[(size_t)(n0 + m) * D_SIZE + gk] : 0.f;
        }
        __syncthreads();

        #pragma unroll
        for (int kk = 0; kk < BK; kk++) {
            float4 a0 = *(const float4*)&As[kk][tm * 4];
            float4 a1 = *(const float4*)&As[kk][64 + tm * 4];
            float4 b0 = *(const float4*)&Bs[kk][tn * 4];
            float4 b1 = *(const float4*)&Bs[kk][64 + tn * 4];
            float a[8] = {a0.x, a0.y, a0.z, a0.w, a1.x, a1.y, a1.z, a1.w};
            float b[8] = {b0.x, b0.y, b0.z, b0.w, b1.x, b1.y, b1.z, b1.w};
            #pragma unroll
            for (int i = 0; i < 8; i++)
                #pragma unroll
                for (int j = 0; j < 8; j++)
                    acc[i][j] = fmaf(a[i], b[j], acc[i][j]);
        }
        __syncthreads();
    }

    // ---- fused epilogue ----
    // column scales (independent of i) hoisted
    float rnp[8];
    int   ncol[8];
    #pragma unroll
    for (int j = 0; j < 8; j++) {
        ncol[j] = n0 + (j >> 2) * 64 + tn * 4 + (j & 3);
        rnp[j]  = g_rnp[ncol[j]];
    }

    #pragma unroll
    for (int i = 0; i < 8; i++) {
        const int m = m0 + (i >> 2) * 64 + tm * 4 + (i & 3);
        const float rm = g_rna[m];
        float rowS = 0.f, rowE = 0.f;
        #pragma unroll
        for (int j = 0; j < 8; j++) {
            float s = acc[i][j] * rm * rnp[j];
            float e = __expf(s * INV_TEMP);
            rowS += s;
            rowE += e;
            if (m == ncol[j]) g_diag[m] = s;   // diagonal (unique writer)
        }
        // reduce across the 16 tn-threads owning this row (contiguous 16 lanes)
        #pragma unroll
        for (int off = 8; off; off >>= 1) {
            rowS += __shfl_down_sync(0xffffffffu, rowS, off, 16);
            rowE += __shfl_down_sync(0xffffffffu, rowE, off, 16);
        }
        if (tn == 0) {
            atomicAdd(&g_sumS[m], rowS);
            atomicAdd(&g_sumexp[m], rowE);
        }
    }
}

// ---------------------------------------------------------------------------
// finalize: per-row loss / stats, reduce to 3 scalars
// ---------------------------------------------------------------------------
__global__ void __launch_bounds__(256) ntxent_finalize(float* __restrict__ out) {
    const int i = blockIdx.x * 256 + threadIdx.x;
    const int lane = threadIdx.x & 31;
    const int warp = threadIdx.x >> 5;

    const float d = g_diag[i];
    float loss = logf(g_sumexp[i]) - INV_TEMP * d;
    float pos  = d;
    float neg  = (g_sumS[i] - d) * (1.0f / (float)(B_SIZE - 1));

    #pragma unroll
    for (int off = 16; off; off >>= 1) {
        loss += __shfl_down_sync(0xffffffffu, loss, off);
        pos  += __shfl_down_sync(0xffffffffu, pos,  off);
        neg  += __shfl_down_sync(0xffffffffu, neg,  off);
    }

    __shared__ float sl[8], sp[8], sn[8];
    if (lane == 0) { sl[warp] = loss; sp[warp] = pos; sn[warp] = neg; }
    __syncthreads();

    if (threadIdx.x == 0) {
        float tl = 0.f, tp = 0.f, tg = 0.f;
        #pragma unroll
        for (int w = 0; w < 8; w++) { tl += sl[w]; tp += sp[w]; tg += sn[w]; }
        const float invB = 1.0f / (float)B_SIZE;
        atomicAdd(out + 0, tl * invB);
        atomicAdd(out + 1, tp * invB);
        atomicAdd(out + 2, tg * invB);
    }
}

// ---------------------------------------------------------------------------
extern "C" void kernel_launch(void* const* d_in, const int* in_sizes, int n_in,
                              void* d_out, int out_size) {
    const float* A = (const float*)d_in[0];
    const float* P = (const float*)d_in[1];
    float* out = (float*)d_out;

    dim3 gi(B_SIZE / 8, 2);
    ntxent_init<<<gi, 256>>>(A, P, out);

    dim3 gg(B_SIZE / BN, B_SIZE / BM);
    ntxent_main<<<gg, 256>>>(A, P);

    ntxent_finalize<<<B_SIZE / 256, 256>>>(out);
}

// round 4
// speedup vs baseline: 5.5616x; 5.5616x over previous
#include <cuda_runtime.h>
#include <cuda_bf16.h>
#include <math.h>
#include <stdint.h>

// NTXent — Round 4: bf16 mma.sync GEMM for sum-exp only; diag & row-sums via
// exact fp32 rank-1 paths (rowsum_i = a_hat_i . sum_j p_hat_j).
//
//   S[i,j] = cos(a_i,p_j);  loss_i = log(sum_j exp(4 S_ij)) - 4 S_ii
//   out = (mean loss, mean diag S, mean offdiag S)

#define B_SIZE 8192
#define D_SIZE 626
#define KPAD   640
#define INV_TEMP 4.0f

#define BM 128
#define BN 128
#define BK 32
#define NITER (KPAD / BK)        // 20
#define STAGES 3
#define ROWB 80                  // smem row stride bytes: 32 bf16 + 8 pad
#define STAGE_BYTES (2 * BM * ROWB)
#define SMEM_BYTES (STAGES * STAGE_BYTES)

// ---------------- persistent scratch ---------------------------------------
__device__ __align__(128) __nv_bfloat16 g_Ab[B_SIZE * KPAD];
__device__ __align__(128) __nv_bfloat16 g_Pb[B_SIZE * KPAD];
__device__ float g_rna[B_SIZE];
__device__ float g_rnp[B_SIZE];
__device__ float g_sumexp[B_SIZE];
__device__ float g_sumS[B_SIZE];
__device__ float g_diag[B_SIZE];
__device__ float g_q[D_SIZE];        // sum_j p_hat_j

// ---------------- helpers ---------------------------------------------------
__device__ __forceinline__ uint32_t smem_u32(const void* p) {
    uint32_t a;
    asm("{ .reg .u64 t; cvta.to.shared.u64 t, %1; cvt.u32.u64 %0, t; }"
        : "=r"(a) : "l"(p));
    return a;
}
__device__ __forceinline__ void cp16(uint32_t dst, const void* src) {
    asm volatile("cp.async.cg.shared.global [%0], [%1], 16;" :: "r"(dst), "l"(src));
}
__device__ __forceinline__ void ldsm_x4(uint32_t* r, uint32_t addr) {
    asm volatile("ldmatrix.sync.aligned.m8n8.x4.shared.b16 {%0,%1,%2,%3}, [%4];"
                 : "=r"(r[0]), "=r"(r[1]), "=r"(r[2]), "=r"(r[3]) : "r"(addr));
}
__device__ __forceinline__ void mma_bf16(float* c, const uint32_t* a,
                                         uint32_t b0, uint32_t b1) {
    asm volatile(
        "mma.sync.aligned.m16n8k16.row.col.f32.bf16.bf16.f32 "
        "{%0,%1,%2,%3}, {%4,%5,%6,%7}, {%8,%9}, {%0,%1,%2,%3};"
        : "+f"(c[0]), "+f"(c[1]), "+f"(c[2]), "+f"(c[3])
        : "r"(a[0]), "r"(a[1]), "r"(a[2]), "r"(a[3]), "r"(b0), "r"(b1));
}

// ---------------------------------------------------------------------------
// prep: per-row norms, exact fp32 diag, bf16 normalized copies, zero accums
// grid B/8 blocks x 256 thr; one warp per row (reads both A and P rows)
// ---------------------------------------------------------------------------
__global__ void __launch_bounds__(256) ntxent_prep(const float* __restrict__ A,
                                                   const float* __restrict__ P,
                                                   float* __restrict__ out) {
    const int warp = threadIdx.x >> 5;
    const int lane = threadIdx.x & 31;
    const int row  = blockIdx.x * 8 + warp;

    const float* ar = A + (size_t)row * D_SIZE;
    const float* pr = P + (size_t)row * D_SIZE;
    float ssa = 0.f, ssp = 0.f, dot = 0.f;
    for (int c = lane; c < D_SIZE; c += 32) {
        float av = ar[c], pv = pr[c];
        ssa = fmaf(av, av, ssa);
        ssp = fmaf(pv, pv, ssp);
        dot = fmaf(av, pv, dot);
    }
    #pragma unroll
    for (int o = 16; o; o >>= 1) {
        ssa += __shfl_xor_sync(0xffffffffu, ssa, o);
        ssp += __shfl_xor_sync(0xffffffffu, ssp, o);
        dot += __shfl_xor_sync(0xffffffffu, dot, o);
    }
    const float rna = rsqrtf(ssa);
    const float rnp = rsqrtf(ssp);

    __nv_bfloat16* ya = g_Ab + (size_t)row * KPAD;
    __nv_bfloat16* yp = g_Pb + (size_t)row * KPAD;
    for (int c = lane; c < KPAD; c += 32) {
        float av = (c < D_SIZE) ? ar[c] * rna : 0.f;
        float pv = (c < D_SIZE) ? pr[c] * rnp : 0.f;
        ya[c] = __float2bfloat16(av);
        yp[c] = __float2bfloat16(pv);
    }
    if (lane == 0) {
        g_rna[row] = rna;
        g_rnp[row] = rnp;
        g_diag[row]   = dot * rna * rnp;   // exact fp32 diagonal
        g_sumexp[row] = 0.f;
    }
    if (blockIdx.x == 0) {
        for (int c = threadIdx.x; c < D_SIZE; c += 256) g_q[c] = 0.f;
        if (threadIdx.x < 3) out[threadIdx.x] = 0.f;
    }
}

// ---------------------------------------------------------------------------
// qsum: g_q[c] = sum_j P[j][c] * rnp[j]   (exact fp32, coalesced)
// grid 64 x 256 thr; block b handles rows [b*128, b*128+128)
// ---------------------------------------------------------------------------
__global__ void __launch_bounds__(256) ntxent_qsum(const float* __restrict__ P) {
    __shared__ float acc[D_SIZE];
    for (int c = threadIdx.x; c < D_SIZE; c += 256) acc[c] = 0.f;
    __syncthreads();

    const int r0 = blockIdx.x * 128;
    for (int r = 0; r < 128; r++) {
        const float s = g_rnp[r0 + r];
        const float* pr = P + (size_t)(r0 + r) * D_SIZE;
        for (int c = threadIdx.x; c < D_SIZE; c += 256)
            acc[c] = fmaf(pr[c], s, acc[c]);
    }
    __syncthreads();
    for (int c = threadIdx.x; c < D_SIZE; c += 256)
        atomicAdd(&g_q[c], acc[c]);
}

// ---------------------------------------------------------------------------
// rowsum: g_sumS[i] = rna[i] * (A[i] . q)   (exact fp32)
// grid B/8 x 256 thr; one warp per row
// ---------------------------------------------------------------------------
__global__ void __launch_bounds__(256) ntxent_rowsum(const float* __restrict__ A) {
    const int warp = threadIdx.x >> 5;
    const int lane = threadIdx.x & 31;
    const int row  = blockIdx.x * 8 + warp;

    const float* ar = A + (size_t)row * D_SIZE;
    float d = 0.f;
    for (int c = lane; c < D_SIZE; c += 32)
        d = fmaf(ar[c], g_q[c], d);
    #pragma unroll
    for (int o = 16; o; o >>= 1) d += __shfl_xor_sync(0xffffffffu, d, o);
    if (lane == 0) g_sumS[row] = d * g_rna[row];
}

// ---------------------------------------------------------------------------
// stage loader: 128x32 bf16 A + 128x32 bf16 B tiles via cp.async 16B
// ---------------------------------------------------------------------------
__device__ __forceinline__ void load_stage(uint32_t sbase, int m0, int n0,
                                           int k0, int tid) {
    const char* asrc = (const char*)g_Ab + ((size_t)m0 * KPAD + k0) * 2;
    const char* bsrc = (const char*)g_Pb + ((size_t)n0 * KPAD + k0) * 2;
    #pragma unroll
    for (int i = 0; i < 2; i++) {
        int seg = tid + i * 256, row = seg >> 2, g = seg & 3;
        cp16(sbase + row * ROWB + g * 16, asrc + (size_t)row * (KPAD * 2) + g * 16);
    }
    #pragma unroll
    for (int i = 0; i < 2; i++) {
        int seg = tid + i * 256, row = seg >> 2, g = seg & 3;
        cp16(sbase + BM * ROWB + row * ROWB + g * 16,
             bsrc + (size_t)row * (KPAD * 2) + g * 16);
    }
    asm volatile("cp.async.commit_group;" ::: "memory");
}

// ---------------------------------------------------------------------------
// main: 128x128 tile, 8 warps (32x64 each), 3-stage cp.async
// epilogue: ONLY sum_j exp(4*S_ij) per row
// ---------------------------------------------------------------------------
__global__ void __launch_bounds__(256) ntxent_hmma() {
    extern __shared__ char smem[];
    const uint32_t sbase = smem_u32(smem);

    const int tid  = threadIdx.x;
    const int lane = tid & 31;
    const int wid  = tid >> 5;
    const int wm   = wid & 3;
    const int wn   = wid >> 2;
    const int m0   = blockIdx.y * BM;
    const int n0   = blockIdx.x * BN;

    float acc[2][8][4];
    #pragma unroll
    for (int i = 0; i < 2; i++)
        #pragma unroll
        for (int j = 0; j < 8; j++)
            #pragma unroll
            for (int q = 0; q < 4; q++) acc[i][j][q] = 0.f;

    load_stage(sbase, m0, n0, 0, tid);
    load_stage(sbase + STAGE_BYTES, m0, n0, BK, tid);

    const int a_row  = lane & 15;
    const int a_koff = ((lane >> 4) & 1) * 16;
    const int b_n    = (lane & 7) | ((lane >> 1) & 8);
    const int b_koff = ((lane >> 3) & 1) * 16;

    for (int c = 0; c < NITER; c++) {
        if (c < NITER - 1) asm volatile("cp.async.wait_group 1;" ::: "memory");
        else               asm volatile("cp.async.wait_group 0;" ::: "memory");
        __syncthreads();

        const uint32_t sA = sbase + (c % STAGES) * STAGE_BYTES;
        const uint32_t sB = sA + BM * ROWB;

        #pragma unroll
        for (int ks = 0; ks < 2; ks++) {
            uint32_t afrag[2][4];
            #pragma unroll
            for (int mi = 0; mi < 2; mi++)
                ldsm_x4(afrag[mi],
                        sA + (wm * 32 + mi * 16 + a_row) * ROWB + ks * 32 + a_koff);

            uint32_t bfrag[4][4];
            #pragma unroll
            for (int np = 0; np < 4; np++)
                ldsm_x4(bfrag[np],
                        sB + (wn * 64 + np * 16 + b_n) * ROWB + ks * 32 + b_koff);

            #pragma unroll
            for (int mi = 0; mi < 2; mi++)
                #pragma unroll
                for (int np = 0; np < 4; np++) {
                    mma_bf16(acc[mi][np * 2 + 0], afrag[mi],
                             bfrag[np][0], bfrag[np][1]);
                    mma_bf16(acc[mi][np * 2 + 1], afrag[mi],
                             bfrag[np][2], bfrag[np][3]);
                }
        }

        if (c + 2 < NITER)
            load_stage(sbase + ((c + 2) % STAGES) * STAGE_BYTES,
                       m0, n0, (c + 2) * BK, tid);
    }

    // ---- epilogue: per-row sum of exp(4*S) ----
    float esum[4] = {0.f, 0.f, 0.f, 0.f};   // [mi*2 + half]
    #pragma unroll
    for (int mi = 0; mi < 2; mi++)
        #pragma unroll
        for (int nt = 0; nt < 8; nt++) {
            const float* cc = acc[mi][nt];
            esum[mi * 2 + 0] += __expf(INV_TEMP * cc[0]) + __expf(INV_TEMP * cc[1]);
            esum[mi * 2 + 1] += __expf(INV_TEMP * cc[2]) + __expf(INV_TEMP * cc[3]);
        }
    #pragma unroll
    for (int q = 0; q < 4; q++)
        #pragma unroll
        for (int o = 1; o < 4; o <<= 1)
            esum[q] += __shfl_xor_sync(0xffffffffu, esum[q], o);
    if ((lane & 3) == 0) {
        #pragma unroll
        for (int q = 0; q < 4; q++) {
            const int row = m0 + wm * 32 + (q >> 1) * 16 + (q & 1) * 8 + (lane >> 2);
            atomicAdd(&g_sumexp[row], esum[q]);
        }
    }
}

// ---------------------------------------------------------------------------
// finalize
// ---------------------------------------------------------------------------
__global__ void __launch_bounds__(256) ntxent_finalize(float* __restrict__ out) {
    const int i = blockIdx.x * 256 + threadIdx.x;
    const int lane = threadIdx.x & 31;
    const int warp = threadIdx.x >> 5;

    const float d = g_diag[i];
    float loss = logf(g_sumexp[i]) - INV_TEMP * d;
    float pos  = d;
    float neg  = (g_sumS[i] - d) * (1.0f / (float)(B_SIZE - 1));

    #pragma unroll
    for (int off = 16; off; off >>= 1) {
        loss += __shfl_down_sync(0xffffffffu, loss, off);
        pos  += __shfl_down_sync(0xffffffffu, pos,  off);
        neg  += __shfl_down_sync(0xffffffffu, neg,  off);
    }
    __shared__ float sl[8], sp[8], sn[8];
    if (lane == 0) { sl[warp] = loss; sp[warp] = pos; sn[warp] = neg; }
    __syncthreads();
    if (threadIdx.x == 0) {
        float tl = 0.f, tp = 0.f, tg = 0.f;
        #pragma unroll
        for (int w = 0; w < 8; w++) { tl += sl[w]; tp += sp[w]; tg += sn[w]; }
        const float invB = 1.0f / (float)B_SIZE;
        atomicAdd(out + 0, tl * invB);
        atomicAdd(out + 1, tp * invB);
        atomicAdd(out + 2, tg * invB);
    }
}

// ---------------------------------------------------------------------------
extern "C" void kernel_launch(void* const* d_in, const int* in_sizes, int n_in,
                              void* d_out, int out_size) {
    const float* A = (const float*)d_in[0];
    const float* P = (const float*)d_in[1];
    float* out = (float*)d_out;

    cudaFuncSetAttribute(ntxent_hmma,
                         cudaFuncAttributeMaxDynamicSharedMemorySize, SMEM_BYTES);

    ntxent_prep<<<B_SIZE / 8, 256>>>(A, P, out);
    ntxent_qsum<<<64, 256>>>(P);
    ntxent_rowsum<<<B_SIZE / 8, 256>>>(A);

    dim3 gg(B_SIZE / BN, B_SIZE / BM);   // (64, 64)
    ntxent_hmma<<<gg, 256, SMEM_BYTES>>>();

    ntxent_finalize<<<B_SIZE / 256, 256>>>(out);
}

// round 5
// speedup vs baseline: 6.0940x; 1.0957x over previous
#include <cuda_runtime.h>
#include <cuda_bf16.h>
#include <math.h>
#include <stdint.h>

// NTXent — Round 5: bf16 mma.sync GEMM (sum-exp only), BK=64, 2-stage
// pipeline, hoisted addressing. Exact fp32 side-paths for diag & row-sums.

#define B_SIZE 8192
#define D_SIZE 626
#define KPAD   640
#define INV_TEMP 4.0f

#define BM 128
#define BN 128
#define BK 64
#define NITER (KPAD / BK)            // 10
#define ROWB 80                       // 32 bf16 + 8B pad
#define PANEL (128 * ROWB)            // 10240: one 128x32 bf16 panel
#define STAGE_BYTES (4 * PANEL)       // A(2 panels) + B(2 panels) = 40960
#define SMEM_BYTES (2 * STAGE_BYTES)  // 81920

// ---------------- persistent scratch ---------------------------------------
__device__ __align__(128) __nv_bfloat16 g_Ab[B_SIZE * KPAD];
__device__ __align__(128) __nv_bfloat16 g_Pb[B_SIZE * KPAD];
__device__ float g_rna[B_SIZE];
__device__ float g_rnp[B_SIZE];
__device__ float g_sumexp[B_SIZE];
__device__ float g_sumS[B_SIZE];
__device__ float g_diag[B_SIZE];
__device__ float g_q[D_SIZE];

// ---------------- helpers ---------------------------------------------------
__device__ __forceinline__ uint32_t smem_u32(const void* p) {
    uint32_t a;
    asm("{ .reg .u64 t; cvta.to.shared.u64 t, %1; cvt.u32.u64 %0, t; }"
        : "=r"(a) : "l"(p));
    return a;
}
__device__ __forceinline__ void cp16(uint32_t dst, const void* src) {
    asm volatile("cp.async.cg.shared.global [%0], [%1], 16;" :: "r"(dst), "l"(src));
}
__device__ __forceinline__ void ldsm_x4(uint32_t* r, uint32_t addr) {
    asm volatile("ldmatrix.sync.aligned.m8n8.x4.shared.b16 {%0,%1,%2,%3}, [%4];"
                 : "=r"(r[0]), "=r"(r[1]), "=r"(r[2]), "=r"(r[3]) : "r"(addr));
}
__device__ __forceinline__ void mma_bf16(float* c, const uint32_t* a,
                                         uint32_t b0, uint32_t b1) {
    asm volatile(
        "mma.sync.aligned.m16n8k16.row.col.f32.bf16.bf16.f32 "
        "{%0,%1,%2,%3}, {%4,%5,%6,%7}, {%8,%9}, {%0,%1,%2,%3};"
        : "+f"(c[0]), "+f"(c[1]), "+f"(c[2]), "+f"(c[3])
        : "r"(a[0]), "r"(a[1]), "r"(a[2]), "r"(a[3]), "r"(b0), "r"(b1));
}

// ---------------------------------------------------------------------------
// prep: norms, exact fp32 diag, normalized bf16 copies, zero accums
// ---------------------------------------------------------------------------
__global__ void __launch_bounds__(256) ntxent_prep(const float* __restrict__ A,
                                                   const float* __restrict__ P,
                                                   float* __restrict__ out) {
    const int warp = threadIdx.x >> 5;
    const int lane = threadIdx.x & 31;
    const int row  = blockIdx.x * 8 + warp;

    const float* ar = A + (size_t)row * D_SIZE;
    const float* pr = P + (size_t)row * D_SIZE;
    float ssa = 0.f, ssp = 0.f, dot = 0.f;
    for (int c = lane; c < D_SIZE; c += 32) {
        float av = ar[c], pv = pr[c];
        ssa = fmaf(av, av, ssa);
        ssp = fmaf(pv, pv, ssp);
        dot = fmaf(av, pv, dot);
    }
    #pragma unroll
    for (int o = 16; o; o >>= 1) {
        ssa += __shfl_xor_sync(0xffffffffu, ssa, o);
        ssp += __shfl_xor_sync(0xffffffffu, ssp, o);
        dot += __shfl_xor_sync(0xffffffffu, dot, o);
    }
    const float rna = rsqrtf(ssa);
    const float rnp = rsqrtf(ssp);

    __nv_bfloat16* ya = g_Ab + (size_t)row * KPAD;
    __nv_bfloat16* yp = g_Pb + (size_t)row * KPAD;
    for (int c = lane; c < KPAD; c += 32) {
        ya[c] = __float2bfloat16((c < D_SIZE) ? ar[c] * rna : 0.f);
        yp[c] = __float2bfloat16((c < D_SIZE) ? pr[c] * rnp : 0.f);
    }
    if (lane == 0) {
        g_rna[row] = rna;
        g_rnp[row] = rnp;
        g_diag[row]   = dot * rna * rnp;
        g_sumexp[row] = 0.f;
    }
    if (blockIdx.x == 0) {
        for (int c = threadIdx.x; c < D_SIZE; c += 256) g_q[c] = 0.f;
        if (threadIdx.x < 3) out[threadIdx.x] = 0.f;
    }
}

// ---------------------------------------------------------------------------
// qsum: g_q[c] = sum_j P[j][c] * rnp[j]   (256 blocks x 32 rows)
// ---------------------------------------------------------------------------
__global__ void __launch_bounds__(256) ntxent_qsum(const float* __restrict__ P) {
    __shared__ float acc[D_SIZE];
    for (int c = threadIdx.x; c < D_SIZE; c += 256) acc[c] = 0.f;
    __syncthreads();

    const int r0 = blockIdx.x * 32;
    for (int r = 0; r < 32; r++) {
        const float s = g_rnp[r0 + r];
        const float* pr = P + (size_t)(r0 + r) * D_SIZE;
        for (int c = threadIdx.x; c < D_SIZE; c += 256)
            acc[c] = fmaf(pr[c], s, acc[c]);
    }
    __syncthreads();
    for (int c = threadIdx.x; c < D_SIZE; c += 256)
        atomicAdd(&g_q[c], acc[c]);
}

// ---------------------------------------------------------------------------
// rowsum: g_sumS[i] = rna[i] * (A[i] . q)
// ---------------------------------------------------------------------------
__global__ void __launch_bounds__(256) ntxent_rowsum(const float* __restrict__ A) {
    const int warp = threadIdx.x >> 5;
    const int lane = threadIdx.x & 31;
    const int row  = blockIdx.x * 8 + warp;

    const float* ar = A + (size_t)row * D_SIZE;
    float d = 0.f;
    for (int c = lane; c < D_SIZE; c += 32)
        d = fmaf(ar[c], g_q[c], d);
    #pragma unroll
    for (int o = 16; o; o >>= 1) d += __shfl_xor_sync(0xffffffffu, d, o);
    if (lane == 0) g_sumS[row] = d * g_rna[row];
}

// ---------------------------------------------------------------------------
// stage loader: A 128x64 + B 128x64 bf16, split into two 32-col panels each
// ---------------------------------------------------------------------------
__device__ __forceinline__ void load_stage(uint32_t sbase, int m0, int n0,
                                           int k0, int tid) {
    const char* asrc = (const char*)g_Ab + ((size_t)m0 * KPAD + k0) * 2;
    const char* bsrc = (const char*)g_Pb + ((size_t)n0 * KPAD + k0) * 2;
    #pragma unroll
    for (int i = 0; i < 4; i++) {           // A: 128 rows x 8 x 16B
        int seg = tid + i * 256, row = seg >> 3, g = seg & 7;
        cp16(sbase + (g >> 2) * PANEL + row * ROWB + (g & 3) * 16,
             asrc + (size_t)row * (KPAD * 2) + g * 16);
    }
    #pragma unroll
    for (int i = 0; i < 4; i++) {           // B: 128 rows x 8 x 16B
        int seg = tid + i * 256, row = seg >> 3, g = seg & 7;
        cp16(sbase + 2 * PANEL + (g >> 2) * PANEL + row * ROWB + (g & 3) * 16,
             bsrc + (size_t)row * (KPAD * 2) + g * 16);
    }
    asm volatile("cp.async.commit_group;" ::: "memory");
}

// ---------------------------------------------------------------------------
// main: 128x128 tile, 8 warps (32x64), BK=64, 2-stage pipeline
// ---------------------------------------------------------------------------
__global__ void __launch_bounds__(256) ntxent_hmma() {
    extern __shared__ char smem[];
    const uint32_t sbase = smem_u32(smem);

    const int tid  = threadIdx.x;
    const int lane = tid & 31;
    const int wid  = tid >> 5;
    const int wm   = wid & 3;
    const int wn   = wid >> 2;
    const int m0   = blockIdx.y * BM;
    const int n0   = blockIdx.x * BN;

    float acc[2][8][4];
    #pragma unroll
    for (int i = 0; i < 2; i++)
        #pragma unroll
        for (int j = 0; j < 8; j++)
            #pragma unroll
            for (int q = 0; q < 4; q++) acc[i][j][q] = 0.f;

    // hoisted ldmatrix base addresses (stage 0)
    const int a_row  = lane & 15;
    const int a_koff = ((lane >> 4) & 1) * 16;
    const int b_n    = (lane & 7) | ((lane >> 1) & 8);
    const int b_koff = ((lane >> 3) & 1) * 16;
    const uint32_t aBase = sbase + (wm * 32 + a_row) * ROWB + a_koff;
    const uint32_t bBase = sbase + 2 * PANEL + (wn * 64 + b_n) * ROWB + b_koff;

    load_stage(sbase, m0, n0, 0, tid);

    for (int c = 0; c < NITER; c++) {
        asm volatile("cp.async.wait_group 0;" ::: "memory");
        __syncthreads();
        if (c + 1 < NITER)
            load_stage(sbase + ((c + 1) & 1) * STAGE_BYTES, m0, n0,
                       (c + 1) * BK, tid);

        const uint32_t soff = (c & 1) * STAGE_BYTES;
        #pragma unroll
        for (int ks = 0; ks < 4; ks++) {
            const uint32_t koff = soff + (ks >> 1) * PANEL + (ks & 1) * 32;

            uint32_t afrag[2][4];
            #pragma unroll
            for (int mi = 0; mi < 2; mi++)
                ldsm_x4(afrag[mi], aBase + koff + mi * (16 * ROWB));

            uint32_t bfrag[4][4];
            #pragma unroll
            for (int np = 0; np < 4; np++)
                ldsm_x4(bfrag[np], bBase + koff + np * (16 * ROWB));

            #pragma unroll
            for (int mi = 0; mi < 2; mi++)
                #pragma unroll
                for (int np = 0; np < 4; np++) {
                    mma_bf16(acc[mi][np * 2 + 0], afrag[mi],
                             bfrag[np][0], bfrag[np][1]);
                    mma_bf16(acc[mi][np * 2 + 1], afrag[mi],
                             bfrag[np][2], bfrag[np][3]);
                }
        }
    }

    // ---- epilogue: per-row sum of exp(4*S) ----
    float esum[4] = {0.f, 0.f, 0.f, 0.f};
    #pragma unroll
    for (int mi = 0; mi < 2; mi++)
        #pragma unroll
        for (int nt = 0; nt < 8; nt++) {
            const float* cc = acc[mi][nt];
            esum[mi * 2 + 0] += __expf(INV_TEMP * cc[0]) + __expf(INV_TEMP * cc[1]);
            esum[mi * 2 + 1] += __expf(INV_TEMP * cc[2]) + __expf(INV_TEMP * cc[3]);
        }
    #pragma unroll
    for (int q = 0; q < 4; q++)
        #pragma unroll
        for (int o = 1; o < 4; o <<= 1)
            esum[q] += __shfl_xor_sync(0xffffffffu, esum[q], o);
    if ((lane & 3) == 0) {
        #pragma unroll
        for (int q = 0; q < 4; q++) {
            const int row = m0 + wm * 32 + (q >> 1) * 16 + (q & 1) * 8 + (lane >> 2);
            atomicAdd(&g_sumexp[row], esum[q]);
        }
    }
}

// ---------------------------------------------------------------------------
// finalize
// ---------------------------------------------------------------------------
__global__ void __launch_bounds__(256) ntxent_finalize(float* __restrict__ out) {
    const int i = blockIdx.x * 256 + threadIdx.x;
    const int lane = threadIdx.x & 31;
    const int warp = threadIdx.x >> 5;

    const float d = g_diag[i];
    float loss = logf(g_sumexp[i]) - INV_TEMP * d;
    float pos  = d;
    float neg  = (g_sumS[i] - d) * (1.0f / (float)(B_SIZE - 1));

    #pragma unroll
    for (int off = 16; off; off >>= 1) {
        loss += __shfl_down_sync(0xffffffffu, loss, off);
        pos  += __shfl_down_sync(0xffffffffu, pos,  off);
        neg  += __shfl_down_sync(0xffffffffu, neg,  off);
    }
    __shared__ float sl[8], sp[8], sn[8];
    if (lane == 0) { sl[warp] = loss; sp[warp] = pos; sn[warp] = neg; }
    __syncthreads();
    if (threadIdx.x == 0) {
        float tl = 0.f, tp = 0.f, tg = 0.f;
        #pragma unroll
        for (int w = 0; w < 8; w++) { tl += sl[w]; tp += sp[w]; tg += sn[w]; }
        const float invB = 1.0f / (float)B_SIZE;
        atomicAdd(out + 0, tl * invB);
        atomicAdd(out + 1, tp * invB);
        atomicAdd(out + 2, tg * invB);
    }
}

// ---------------------------------------------------------------------------
extern "C" void kernel_launch(void* const* d_in, const int* in_sizes, int n_in,
                              void* d_out, int out_size) {
    const float* A = (const float*)d_in[0];
    const float* P = (const float*)d_in[1];
    float* out = (float*)d_out;

    cudaFuncSetAttribute(ntxent_hmma,
                         cudaFuncAttributeMaxDynamicSharedMemorySize, SMEM_BYTES);

    ntxent_prep<<<B_SIZE / 8, 256>>>(A, P, out);
    ntxent_qsum<<<256, 256>>>(P);
    ntxent_rowsum<<<B_SIZE / 8, 256>>>(A);

    dim3 gg(B_SIZE / BN, B_SIZE / BM);   // (64, 64)
    ntxent_hmma<<<gg, 256, SMEM_BYTES>>>();

    ntxent_finalize<<<B_SIZE / 256, 256>>>(out);
}